// round 12
// baseline (speedup 1.0000x reference)
#include <cuda_runtime.h>
#include <cuda_fp16.h>
#include <math_constants.h>

#define NN 100000
#define NE 1000000
#define DD 64
#define ECAP 128
#define XRS 72   // x row stride in floats: 288 B, 16B-aligned (70 trapped: 280 B)

// ---- static scratch ----
__device__ __align__(16) __half d_hh[NN * DD];  // fp16 projected features
__device__ __align__(16) float  d_x[NN * DD];   // fp32 layer ping buffer
__device__ float d_asrc[NN];
__device__ float d_adst[NN];
__device__ int   d_cnt[NN];
__device__ int   d_ell[NN * ECAP];

#define FMA2(acc, a, b) \
    asm("fma.rn.f32x2 %0, %1, %2, %3;" : "=l"(acc) : "l"(a), "l"(b), "l"(acc))

union U64F2 { unsigned long long u; float f[2]; };

// ================= adjacency build =================

__global__ void zero_k() {
    int i = blockIdx.x * blockDim.x + threadIdx.x;
    if (i < NN) d_cnt[i] = 0;
}

__global__ void ell_k(const int* __restrict__ src, const int* __restrict__ dst) {
    int e = blockIdx.x * blockDim.x + threadIdx.x;
    if (e < NE) {
        int d = dst[e];
        int slot = atomicAdd(&d_cnt[d], 1);
        if (slot < ECAP) d_ell[d * ECAP + slot] = src[e];
    }
}

// profiler-alignment pad: shifts GEMM to captured launch index 3
__global__ void pad_k() {}

// ================= GEMM h = x @ W: k-pair FFMA2, transpose-free ================
// acc packed over k-parity (lo = even k, hi = odd k; o = lo+hi at the end).
// x staged ROW-major (stride 72 = 288 B, 16B-aligned vector stores, broadcast loads);
// W staged col-major (stride 66). Thread cols = {c4, c4+16, c4+32, c4+48}
// -> w-load banks 2*c4+k : conflict-free. Zero PACKDUP in mainloop.

__global__ __launch_bounds__(256) void gemm_attn_k(
        const float* __restrict__ x_ext, int use_internal,
        const float* __restrict__ W,
        const float* __restrict__ att_s, const float* __restrict__ att_d)
{
    const float* __restrict__ x = use_internal ? d_x : x_ext;
    __shared__ __align__(16) float wsT[64 * 66];    // [c][k] 16.5 KB
    __shared__ __align__(16) float xs[128 * XRS];   // [r][k] 36.0 KB
    int tid  = threadIdx.x;
    int row0 = blockIdx.x * 128;

    for (int i = tid; i < 1024; i += 256) {
        int k = i >> 4, c4i = i & 15;
        float4 v = ((const float4*)W)[i];           // W[k][4c..4c+3]
        wsT[(c4i * 4 + 0) * 66 + k] = v.x;
        wsT[(c4i * 4 + 1) * 66 + k] = v.y;
        wsT[(c4i * 4 + 2) * 66 + k] = v.z;
        wsT[(c4i * 4 + 3) * 66 + k] = v.w;
    }
    for (int i = tid; i < 2048; i += 256) {
        int r = i >> 4, c4i = i & 15;
        float4 v = make_float4(0.f, 0.f, 0.f, 0.f);
        int gr = row0 + r;
        if (gr < NN) v = ((const float4*)x)[gr * 16 + c4i];
        *(float4*)&xs[r * XRS + c4i * 4] = v;
    }
    __syncthreads();

    int c4 = tid & 15;            // col base; this thread's cols: c4 + 16j
    int ty = (tid >> 4) * 8;      // 8 rows

    unsigned long long acc[8][4];
#pragma unroll
    for (int i = 0; i < 8; i++)
#pragma unroll
        for (int j = 0; j < 4; j++) acc[i][j] = 0ull;

    for (int k = 0; k < 64; k += 2) {
        unsigned long long wc0 = *(const unsigned long long*)&wsT[(c4     ) * 66 + k];
        unsigned long long wc1 = *(const unsigned long long*)&wsT[(c4 + 16) * 66 + k];
        unsigned long long wc2 = *(const unsigned long long*)&wsT[(c4 + 32) * 66 + k];
        unsigned long long wc3 = *(const unsigned long long*)&wsT[(c4 + 48) * 66 + k];
#pragma unroll
        for (int i = 0; i < 8; i++) {
            unsigned long long xr =
                *(const unsigned long long*)&xs[(ty + i) * XRS + k];
            FMA2(acc[i][0], xr, wc0);
            FMA2(acc[i][1], xr, wc1);
            FMA2(acc[i][2], xr, wc2);
            FMA2(acc[i][3], xr, wc3);
        }
    }

    float as0 = att_s[c4],      as1 = att_s[c4 + 16];
    float as2 = att_s[c4 + 32], as3 = att_s[c4 + 48];
    float ad0 = att_d[c4],      ad1 = att_d[c4 + 16];
    float ad2 = att_d[c4 + 32], ad3 = att_d[c4 + 48];

#pragma unroll
    for (int i = 0; i < 8; i++) {
        U64F2 u0, u1, u2, u3;
        u0.u = acc[i][0]; u1.u = acc[i][1];
        u2.u = acc[i][2]; u3.u = acc[i][3];
        float o0 = u0.f[0] + u0.f[1];
        float o1 = u1.f[0] + u1.f[1];
        float o2 = u2.f[0] + u2.f[1];
        float o3 = u3.f[0] + u3.f[1];

        float ps = o0*as0 + o1*as1 + o2*as2 + o3*as3;
        float pd = o0*ad0 + o1*ad1 + o2*ad2 + o3*ad3;
#pragma unroll
        for (int off = 8; off; off >>= 1) {
            ps += __shfl_xor_sync(0xffffffffu, ps, off, 16);
            pd += __shfl_xor_sync(0xffffffffu, pd, off, 16);
        }
        int gr = row0 + ty + i;
        if (gr < NN) {
            __half* hp = d_hh + gr * 64 + c4;
            hp[0]  = __float2half_rn(o0);
            hp[16] = __float2half_rn(o1);
            hp[32] = __float2half_rn(o2);
            hp[48] = __float2half_rn(o3);
            if (c4 == 0) { d_asrc[gr] = ps; d_adst[gr] = pd; }
        }
    }
}

// ================= segment softmax + weighted gather (HALF-WARP per node) ======
// Denominator via one width-16 shfl-reduce BEFORE the gather (loop is pure FMA).

__global__ __launch_bounds__(256, 8) void aggregate_k(
        const float* __restrict__ bias, float* __restrict__ out_ext, int to_internal)
{
    __shared__ float2 sew[8][2][32];
    float* __restrict__ out = to_internal ? d_x : out_ext;
    int w    = threadIdx.x >> 5;
    int lane = threadIdx.x & 31;
    int half = lane >> 4, li = lane & 15;
    unsigned hm = 0xFFFFu << (half * 16);
    int node = (blockIdx.x * 8 + w) * 2 + half;   // 6250*8*2 = 100000 exactly

    int deg = d_cnt[node];
    deg = deg > ECAP ? ECAP : deg;
    float4 b4 = ((const float4*)bias)[li];
    float4* op = (float4*)out + node * 16 + li;
    const int* row = d_ell + node * ECAP;

    if (deg <= 32) {
        float adv = d_adst[node];
        int   s0 = row[li < deg ? li : (deg > 0 ? deg - 1 : 0)];
        float e0 = d_asrc[s0] + adv;
        e0 = e0 > 0.f ? e0 : 0.2f * e0;
        float mx = li < deg ? e0 : -CUDART_INF_F;
        int s1 = 0; float e1 = 0.f;
        if (deg > 16) {
            int i2 = li + 16;
            s1 = row[i2 < deg ? i2 : deg - 1];
            e1 = d_asrc[s1] + adv;
            e1 = e1 > 0.f ? e1 : 0.2f * e1;
            if (i2 < deg) mx = fmaxf(mx, e1);
        }
#pragma unroll
        for (int off = 8; off; off >>= 1)
            mx = fmaxf(mx, __shfl_xor_sync(hm, mx, off, 16));
        float wt0 = li < deg ? __expf(e0 - mx) : 0.f;
        float wt1 = (deg > 16 && (li + 16) < deg) ? __expf(e1 - mx) : 0.f;
        sew[w][half][li] = make_float2(__int_as_float(s0), wt0);
        if (deg > 16)
            sew[w][half][li + 16] = make_float2(__int_as_float(s1), wt1);
        float sm = wt0 + wt1;
#pragma unroll
        for (int off = 8; off; off >>= 1)
            sm += __shfl_xor_sync(hm, sm, off, 16);
        float inv = 1.f / (sm + 1e-16f);
        __syncwarp(hm);

        float ax = 0.f, ay = 0.f, az = 0.f, aw = 0.f;
        int iters = (deg + 3) >> 2;
        for (int it = 0; it < iters; it++) {
            int base = it * 4;
            float2 p0 = sew[w][half][base + 0];
            float2 p1 = sew[w][half][base + 1];
            float2 p2 = sew[w][half][base + 2];
            float2 p3 = sew[w][half][base + 3];
            uint2 h0 = ((const uint2*)(d_hh + __float_as_int(p0.x) * 64))[li];
            uint2 h1 = ((const uint2*)(d_hh + __float_as_int(p1.x) * 64))[li];
            uint2 h2 = ((const uint2*)(d_hh + __float_as_int(p2.x) * 64))[li];
            uint2 h3 = ((const uint2*)(d_hh + __float_as_int(p3.x) * 64))[li];
            {
                float2 lo = __half22float2(*(__half2*)&h0.x);
                float2 hi = __half22float2(*(__half2*)&h0.y);
                ax += p0.y * lo.x; ay += p0.y * lo.y;
                az += p0.y * hi.x; aw += p0.y * hi.y;
            }
            {
                float2 lo = __half22float2(*(__half2*)&h1.x);
                float2 hi = __half22float2(*(__half2*)&h1.y);
                ax += p1.y * lo.x; ay += p1.y * lo.y;
                az += p1.y * hi.x; aw += p1.y * hi.y;
            }
            {
                float2 lo = __half22float2(*(__half2*)&h2.x);
                float2 hi = __half22float2(*(__half2*)&h2.y);
                ax += p2.y * lo.x; ay += p2.y * lo.y;
                az += p2.y * hi.x; aw += p2.y * hi.y;
            }
            {
                float2 lo = __half22float2(*(__half2*)&h3.x);
                float2 hi = __half22float2(*(__half2*)&h3.y);
                ax += p3.y * lo.x; ay += p3.y * lo.y;
                az += p3.y * hi.x; aw += p3.y * hi.y;
            }
        }
        float4 r;
        r.x = ax * inv + b4.x;
        r.y = ay * inv + b4.y;
        r.z = az * inv + b4.z;
        r.w = aw * inv + b4.w;
        *op = r;
    } else {
        // essentially-never path (deg in (32,128])
        float adv = d_adst[node];
        float mx = -CUDART_INF_F;
        for (int j = li; j < deg; j += 16) {
            float e = d_asrc[row[j]] + adv;
            e = e > 0.f ? e : 0.2f * e;
            mx = fmaxf(mx, e);
        }
#pragma unroll
        for (int off = 8; off; off >>= 1)
            mx = fmaxf(mx, __shfl_xor_sync(hm, mx, off, 16));
        float sm = 0.f;
        for (int j = li; j < deg; j += 16) {
            float e = d_asrc[row[j]] + adv;
            e = e > 0.f ? e : 0.2f * e;
            sm += __expf(e - mx);
        }
#pragma unroll
        for (int off = 8; off; off >>= 1)
            sm += __shfl_xor_sync(hm, sm, off, 16);
        float inv = 1.f / (sm + 1e-16f);

        float ax = 0.f, ay = 0.f, az = 0.f, aw = 0.f;
        for (int j = 0; j < deg; j++) {
            int s = row[j];
            float e = d_asrc[s] + adv;
            e = e > 0.f ? e : 0.2f * e;
            float wt = __expf(e - mx);
            uint2 hv = ((const uint2*)(d_hh + s * 64))[li];
            float2 lo = __half22float2(*(__half2*)&hv.x);
            float2 hi = __half22float2(*(__half2*)&hv.y);
            ax += wt * lo.x; ay += wt * lo.y;
            az += wt * hi.x; aw += wt * hi.y;
        }
        float4 r;
        r.x = ax * inv + b4.x;
        r.y = ay * inv + b4.y;
        r.z = az * inv + b4.z;
        r.w = aw * inv + b4.w;
        *op = r;
    }
}

// ================= launch =================

extern "C" void kernel_launch(void* const* d_in, const int* in_sizes, int n_in,
                              void* d_out, int out_size)
{
    const float* g     = (const float*)d_in[0];
    const int*   ei    = (const int*)  d_in[1];
    const float* W     = (const float*)d_in[2];
    const float* att_s = (const float*)d_in[3];
    const float* att_d = (const float*)d_in[4];
    const float* bias  = (const float*)d_in[5];
    float* out = (float*)d_out;

    const int* src = ei;
    const int* dst = ei + NE;

    zero_k<<<(NN + 255) / 256, 256>>>();
    ell_k<<<(NE + 255) / 256, 256>>>(src, dst);
    pad_k<<<1, 32>>>();   // shifts GEMM to ncu's captured launch slot (#3)

    const int gemm_blocks = (NN + 127) / 128;   // 782
    const int agg_blocks  = NN / 16;            // 6250, exact

    for (int L = 0; L < 4; L++) {
        gemm_attn_k<<<gemm_blocks, 256>>>(L == 0 ? g : nullptr, L == 0 ? 0 : 1,
                                          W, att_s, att_d);
        aggregate_k<<<agg_blocks, 256>>>(bias, L == 3 ? out : nullptr,
                                         L == 3 ? 0 : 1);
    }
}

// round 13
// speedup vs baseline: 1.0340x; 1.0340x over previous
#include <cuda_runtime.h>
#include <cuda_fp16.h>
#include <math_constants.h>

#define NN 100000
#define NE 1000000
#define DD 64
#define ECAP 128
#define XRS 72   // x row stride in floats: 288 B, 16B-aligned

// ---- static scratch ----
__device__ __align__(16) __half d_hh[NN * DD];  // fp16 projected features
__device__ __align__(16) float  d_x[NN * DD];   // fp32 layer ping buffer
__device__ float d_asrc[NN];
__device__ float d_adst[NN];
__device__ int   d_cnt[NN];
__device__ int   d_ell[NN * ECAP];

#define FMA2(acc, a, b) \
    asm("fma.rn.f32x2 %0, %1, %2, %3;" : "=l"(acc) : "l"(a), "l"(b), "l"(acc))

union U64F2 { unsigned long long u; float f[2]; };

// ================= adjacency build =================

__global__ void zero_k() {
    int i = blockIdx.x * blockDim.x + threadIdx.x;
    if (i < NN) d_cnt[i] = 0;
}

__global__ void ell_k(const int* __restrict__ src, const int* __restrict__ dst) {
    int e = blockIdx.x * blockDim.x + threadIdx.x;
    if (e < NE) {
        int d = dst[e];
        int slot = atomicAdd(&d_cnt[d], 1);
        if (slot < ECAP) d_ell[d * ECAP + slot] = src[e];
    }
}

// profiler-alignment pad: keeps GEMM at captured launch index 3
__global__ void pad_k() {}

// ================= GEMM h = x @ W: k-pair FFMA2, 64-row tile ===================
// acc over k-parity: 4 rows x 4 cols = 16 u64 accs (32 regs).
// x row-major (stride 72), W col-major (stride 66); cols {c4,+16,+32,+48}
// -> conflict-free 8B smem loads, zero PACKDUP. h staged via smem -> STG.128.

__global__ __launch_bounds__(256) void gemm_attn_k(
        const float* __restrict__ x_ext, int use_internal,
        const float* __restrict__ W,
        const float* __restrict__ att_s, const float* __restrict__ att_d)
{
    const float* __restrict__ x = use_internal ? d_x : x_ext;
    __shared__ __align__(16) float wsT[64 * 66];   // [c][k] 16.5 KB
    __shared__ __align__(16) float xs[64 * XRS];   // [r][k] 18.0 KB (reused as h-buf)
    int tid  = threadIdx.x;
    int row0 = blockIdx.x * 64;

    for (int i = tid; i < 1024; i += 256) {
        int k = i >> 4, c4i = i & 15;
        float4 v = ((const float4*)W)[i];          // W[k][4c..4c+3]
        wsT[(c4i * 4 + 0) * 66 + k] = v.x;
        wsT[(c4i * 4 + 1) * 66 + k] = v.y;
        wsT[(c4i * 4 + 2) * 66 + k] = v.z;
        wsT[(c4i * 4 + 3) * 66 + k] = v.w;
    }
    for (int i = tid; i < 1024; i += 256) {
        int r = i >> 4, c4i = i & 15;
        float4 v = make_float4(0.f, 0.f, 0.f, 0.f);
        int gr = row0 + r;
        if (gr < NN) v = ((const float4*)x)[gr * 16 + c4i];
        *(float4*)&xs[r * XRS + c4i * 4] = v;
    }
    __syncthreads();

    int c4 = tid & 15;            // cols: c4 + 16j
    int ty = (tid >> 4) * 4;      // 4 rows

    unsigned long long acc[4][4];
#pragma unroll
    for (int i = 0; i < 4; i++)
#pragma unroll
        for (int j = 0; j < 4; j++) acc[i][j] = 0ull;

    for (int k = 0; k < 64; k += 2) {
        unsigned long long wc0 = *(const unsigned long long*)&wsT[(c4     ) * 66 + k];
        unsigned long long wc1 = *(const unsigned long long*)&wsT[(c4 + 16) * 66 + k];
        unsigned long long wc2 = *(const unsigned long long*)&wsT[(c4 + 32) * 66 + k];
        unsigned long long wc3 = *(const unsigned long long*)&wsT[(c4 + 48) * 66 + k];
#pragma unroll
        for (int i = 0; i < 4; i++) {
            unsigned long long xr =
                *(const unsigned long long*)&xs[(ty + i) * XRS + k];
            FMA2(acc[i][0], xr, wc0);
            FMA2(acc[i][1], xr, wc1);
            FMA2(acc[i][2], xr, wc2);
            FMA2(acc[i][3], xr, wc3);
        }
    }

    float as0 = att_s[c4],      as1 = att_s[c4 + 16];
    float as2 = att_s[c4 + 32], as3 = att_s[c4 + 48];
    float ad0 = att_d[c4],      ad1 = att_d[c4 + 16];
    float ad2 = att_d[c4 + 32], ad3 = att_d[c4 + 48];

    float o[4][4];
    float ps[4], pd[4];
#pragma unroll
    for (int i = 0; i < 4; i++) {
        U64F2 u0, u1, u2, u3;
        u0.u = acc[i][0]; u1.u = acc[i][1];
        u2.u = acc[i][2]; u3.u = acc[i][3];
        o[i][0] = u0.f[0] + u0.f[1];
        o[i][1] = u1.f[0] + u1.f[1];
        o[i][2] = u2.f[0] + u2.f[1];
        o[i][3] = u3.f[0] + u3.f[1];
        ps[i] = o[i][0]*as0 + o[i][1]*as1 + o[i][2]*as2 + o[i][3]*as3;
        pd[i] = o[i][0]*ad0 + o[i][1]*ad1 + o[i][2]*ad2 + o[i][3]*ad3;
#pragma unroll
        for (int off = 8; off; off >>= 1) {
            ps[i] += __shfl_xor_sync(0xffffffffu, ps[i], off, 16);
            pd[i] += __shfl_xor_sync(0xffffffffu, pd[i], off, 16);
        }
    }

    __syncthreads();                       // all xs reads done -> reuse as h-buf
    __half* hb = (__half*)xs;              // 64 x 64 halves = 8 KB
#pragma unroll
    for (int i = 0; i < 4; i++) {
        int r = ty + i;
        hb[r * 64 + c4]      = __float2half_rn(o[i][0]);
        hb[r * 64 + c4 + 16] = __float2half_rn(o[i][1]);
        hb[r * 64 + c4 + 32] = __float2half_rn(o[i][2]);
        hb[r * 64 + c4 + 48] = __float2half_rn(o[i][3]);
        int gr = row0 + r;
        if (c4 == 0 && gr < NN) { d_asrc[gr] = ps[i]; d_adst[gr] = pd[i]; }
    }
    __syncthreads();

    // coalesced copy: 64 rows x 128 B = 512 uint4; 2 per thread
    const uint4* hb4 = (const uint4*)hb;
#pragma unroll
    for (int t = 0; t < 2; t++) {
        int i = tid + t * 256;             // 0..511
        int gr = row0 + (i >> 3);          // 8 uint4 per row
        if (gr < NN)
            ((uint4*)d_hh)[row0 * 8 + i] = hb4[i];
    }
}

// ================= segment softmax + weighted gather (HALF-WARP per node) ======
// Denominator via one width-16 shfl-reduce BEFORE the gather (loop is pure FMA).

__global__ __launch_bounds__(256, 8) void aggregate_k(
        const float* __restrict__ bias, float* __restrict__ out_ext, int to_internal)
{
    __shared__ float2 sew[8][2][32];
    float* __restrict__ out = to_internal ? d_x : out_ext;
    int w    = threadIdx.x >> 5;
    int lane = threadIdx.x & 31;
    int half = lane >> 4, li = lane & 15;
    unsigned hm = 0xFFFFu << (half * 16);
    int node = (blockIdx.x * 8 + w) * 2 + half;   // 6250*8*2 = 100000 exactly

    int deg = d_cnt[node];
    deg = deg > ECAP ? ECAP : deg;
    float4 b4 = ((const float4*)bias)[li];
    float4* op = (float4*)out + node * 16 + li;
    const int* row = d_ell + node * ECAP;

    if (deg <= 32) {
        float adv = d_adst[node];
        int   s0 = row[li < deg ? li : (deg > 0 ? deg - 1 : 0)];
        float e0 = d_asrc[s0] + adv;
        e0 = e0 > 0.f ? e0 : 0.2f * e0;
        float mx = li < deg ? e0 : -CUDART_INF_F;
        int s1 = 0; float e1 = 0.f;
        if (deg > 16) {
            int i2 = li + 16;
            s1 = row[i2 < deg ? i2 : deg - 1];
            e1 = d_asrc[s1] + adv;
            e1 = e1 > 0.f ? e1 : 0.2f * e1;
            if (i2 < deg) mx = fmaxf(mx, e1);
        }
#pragma unroll
        for (int off = 8; off; off >>= 1)
            mx = fmaxf(mx, __shfl_xor_sync(hm, mx, off, 16));
        float wt0 = li < deg ? __expf(e0 - mx) : 0.f;
        float wt1 = (deg > 16 && (li + 16) < deg) ? __expf(e1 - mx) : 0.f;
        sew[w][half][li] = make_float2(__int_as_float(s0), wt0);
        if (deg > 16)
            sew[w][half][li + 16] = make_float2(__int_as_float(s1), wt1);
        float sm = wt0 + wt1;
#pragma unroll
        for (int off = 8; off; off >>= 1)
            sm += __shfl_xor_sync(hm, sm, off, 16);
        float inv = 1.f / (sm + 1e-16f);
        __syncwarp(hm);

        float ax = 0.f, ay = 0.f, az = 0.f, aw = 0.f;
        int iters = (deg + 3) >> 2;
        for (int it = 0; it < iters; it++) {
            int base = it * 4;
            float2 p0 = sew[w][half][base + 0];
            float2 p1 = sew[w][half][base + 1];
            float2 p2 = sew[w][half][base + 2];
            float2 p3 = sew[w][half][base + 3];
            uint2 h0 = ((const uint2*)(d_hh + __float_as_int(p0.x) * 64))[li];
            uint2 h1 = ((const uint2*)(d_hh + __float_as_int(p1.x) * 64))[li];
            uint2 h2 = ((const uint2*)(d_hh + __float_as_int(p2.x) * 64))[li];
            uint2 h3 = ((const uint2*)(d_hh + __float_as_int(p3.x) * 64))[li];
            {
                float2 lo = __half22float2(*(__half2*)&h0.x);
                float2 hi = __half22float2(*(__half2*)&h0.y);
                ax += p0.y * lo.x; ay += p0.y * lo.y;
                az += p0.y * hi.x; aw += p0.y * hi.y;
            }
            {
                float2 lo = __half22float2(*(__half2*)&h1.x);
                float2 hi = __half22float2(*(__half2*)&h1.y);
                ax += p1.y * lo.x; ay += p1.y * lo.y;
                az += p1.y * hi.x; aw += p1.y * hi.y;
            }
            {
                float2 lo = __half22float2(*(__half2*)&h2.x);
                float2 hi = __half22float2(*(__half2*)&h2.y);
                ax += p2.y * lo.x; ay += p2.y * lo.y;
                az += p2.y * hi.x; aw += p2.y * hi.y;
            }
            {
                float2 lo = __half22float2(*(__half2*)&h3.x);
                float2 hi = __half22float2(*(__half2*)&h3.y);
                ax += p3.y * lo.x; ay += p3.y * lo.y;
                az += p3.y * hi.x; aw += p3.y * hi.y;
            }
        }
        float4 r;
        r.x = ax * inv + b4.x;
        r.y = ay * inv + b4.y;
        r.z = az * inv + b4.z;
        r.w = aw * inv + b4.w;
        *op = r;
    } else {
        // essentially-never path (deg in (32,128])
        float adv = d_adst[node];
        float mx = -CUDART_INF_F;
        for (int j = li; j < deg; j += 16) {
            float e = d_asrc[row[j]] + adv;
            e = e > 0.f ? e : 0.2f * e;
            mx = fmaxf(mx, e);
        }
#pragma unroll
        for (int off = 8; off; off >>= 1)
            mx = fmaxf(mx, __shfl_xor_sync(hm, mx, off, 16));
        float sm = 0.f;
        for (int j = li; j < deg; j += 16) {
            float e = d_asrc[row[j]] + adv;
            e = e > 0.f ? e : 0.2f * e;
            sm += __expf(e - mx);
        }
#pragma unroll
        for (int off = 8; off; off >>= 1)
            sm += __shfl_xor_sync(hm, sm, off, 16);
        float inv = 1.f / (sm + 1e-16f);

        float ax = 0.f, ay = 0.f, az = 0.f, aw = 0.f;
        for (int j = 0; j < deg; j++) {
            int s = row[j];
            float e = d_asrc[s] + adv;
            e = e > 0.f ? e : 0.2f * e;
            float wt = __expf(e - mx);
            uint2 hv = ((const uint2*)(d_hh + s * 64))[li];
            float2 lo = __half22float2(*(__half2*)&hv.x);
            float2 hi = __half22float2(*(__half2*)&hv.y);
            ax += wt * lo.x; ay += wt * lo.y;
            az += wt * hi.x; aw += wt * hi.y;
        }
        float4 r;
        r.x = ax * inv + b4.x;
        r.y = ay * inv + b4.y;
        r.z = az * inv + b4.z;
        r.w = aw * inv + b4.w;
        *op = r;
    }
}

// ================= launch =================

extern "C" void kernel_launch(void* const* d_in, const int* in_sizes, int n_in,
                              void* d_out, int out_size)
{
    const float* g     = (const float*)d_in[0];
    const int*   ei    = (const int*)  d_in[1];
    const float* W     = (const float*)d_in[2];
    const float* att_s = (const float*)d_in[3];
    const float* att_d = (const float*)d_in[4];
    const float* bias  = (const float*)d_in[5];
    float* out = (float*)d_out;

    const int* src = ei;
    const int* dst = ei + NE;

    zero_k<<<(NN + 255) / 256, 256>>>();
    ell_k<<<(NE + 255) / 256, 256>>>(src, dst);
    pad_k<<<1, 32>>>();   // keeps GEMM at ncu's captured launch slot (#3)

    const int gemm_blocks = (NN + 63) / 64;     // 1563
    const int agg_blocks  = NN / 16;            // 6250, exact

    for (int L = 0; L < 4; L++) {
        gemm_attn_k<<<gemm_blocks, 256>>>(L == 0 ? g : nullptr, L == 0 ? 0 : 1,
                                          W, att_s, att_d);
        aggregate_k<<<agg_blocks, 256>>>(bias, L == 3 ? out : nullptr,
                                         L == 3 ? 0 : 1);
    }
}

// round 14
// speedup vs baseline: 1.0871x; 1.0514x over previous
#include <cuda_runtime.h>
#include <cuda_fp16.h>
#include <math_constants.h>

#define NN 100000
#define NE 1000000
#define DD 64
#define ECAP 128
#define XST 132

// ---- static scratch ----
__device__ __align__(16) __half d_hh[NN * DD];  // fp16 projected features
__device__ __align__(16) float  d_x[NN * DD];   // fp32 layer ping buffer
__device__ float d_asrc[NN];
__device__ float d_adst[NN];
__device__ int   d_cnt[NN];
__device__ int   d_ell[NN * ECAP];

#define FMA2(acc, a, b) \
    asm("fma.rn.f32x2 %0, %1, %2, %3;" : "=l"(acc) : "l"(a), "l"(b), "l"(acc))
#define PACKDUP(dst, v) \
    asm("mov.b64 %0, {%1, %1};" : "=l"(dst) : "f"(v))

union U64F2 { unsigned long long u; float f[2]; };

// ================= adjacency build =================

__global__ void zero_k() {
    int i = blockIdx.x * blockDim.x + threadIdx.x;
    if (i < NN) d_cnt[i] = 0;
}

__global__ void ell_k(const int* __restrict__ src, const int* __restrict__ dst) {
    int e = blockIdx.x * blockDim.x + threadIdx.x;
    if (e < NE) {
        int d = dst[e];
        int slot = atomicAdd(&d_cnt[d], 1);
        if (slot < ECAP) d_ell[d * ECAP + slot] = src[e];
    }
}

// profiler-alignment pad: keeps GEMM at captured launch index 3
__global__ void pad_k() {}

// ================= GEMM (R10 version): row-pair FFMA2, 128x64 tile =============
// Accumulators packed along ROW PAIRS: f32x2 x-operand is a free 16B LDS of
// adjacent rows in the transposed tile; only W needs PACKDUP (4/k).

__global__ __launch_bounds__(256) void gemm_attn_k(
        const float* __restrict__ x_ext, int use_internal,
        const float* __restrict__ W,
        const float* __restrict__ att_s, const float* __restrict__ att_d)
{
    const float* __restrict__ x = use_internal ? d_x : x_ext;
    __shared__ __align__(16) float ws[64 * 64];     // 16 KB
    __shared__ __align__(16) float xsT[64 * XST];   // 33.8 KB
    int tid  = threadIdx.x;
    int row0 = blockIdx.x * 128;

    for (int i = tid; i < 1024; i += 256)
        ((float4*)ws)[i] = ((const float4*)W)[i];
    for (int i = tid; i < 2048; i += 256) {
        int r = i >> 4, c4 = i & 15;
        float4 v = make_float4(0.f, 0.f, 0.f, 0.f);
        int gr = row0 + r;
        if (gr < NN) v = ((const float4*)x)[gr * 16 + c4];
        int c = c4 * 4;
        xsT[(c + 0) * XST + r] = v.x;
        xsT[(c + 1) * XST + r] = v.y;
        xsT[(c + 2) * XST + r] = v.z;
        xsT[(c + 3) * XST + r] = v.w;
    }
    __syncthreads();

    int tx = (tid & 15) * 4;
    int ty = (tid >> 4) * 8;

    unsigned long long acc[4][4];
#pragma unroll
    for (int rp = 0; rp < 4; rp++)
#pragma unroll
        for (int c = 0; c < 4; c++) acc[rp][c] = 0ull;

#pragma unroll 8
    for (int k = 0; k < 64; k++) {
        ulonglong2 xpA = *(const ulonglong2*)&xsT[k * XST + ty];
        ulonglong2 xpB = *(const ulonglong2*)&xsT[k * XST + ty + 4];
        float4 wv = *(const float4*)&ws[k * 64 + tx];
        unsigned long long w0, w1, w2, w3;
        PACKDUP(w0, wv.x); PACKDUP(w1, wv.y);
        PACKDUP(w2, wv.z); PACKDUP(w3, wv.w);
        unsigned long long xp[4] = {xpA.x, xpA.y, xpB.x, xpB.y};
#pragma unroll
        for (int rp = 0; rp < 4; rp++) {
            FMA2(acc[rp][0], xp[rp], w0);
            FMA2(acc[rp][1], xp[rp], w1);
            FMA2(acc[rp][2], xp[rp], w2);
            FMA2(acc[rp][3], xp[rp], w3);
        }
    }

    float4 as4 = ((const float4*)att_s)[tid & 15];
    float4 ad4 = ((const float4*)att_d)[tid & 15];

#pragma unroll
    for (int rp = 0; rp < 4; rp++) {
        U64F2 c0, c1, c2, c3;
        c0.u = acc[rp][0]; c1.u = acc[rp][1];
        c2.u = acc[rp][2]; c3.u = acc[rp][3];
#pragma unroll
        for (int h = 0; h < 2; h++) {
            float o0 = c0.f[h], o1 = c1.f[h], o2 = c2.f[h], o3 = c3.f[h];
            float ps = o0*as4.x + o1*as4.y + o2*as4.z + o3*as4.w;
            float pd = o0*ad4.x + o1*ad4.y + o2*ad4.z + o3*ad4.w;
#pragma unroll
            for (int off = 8; off; off >>= 1) {
                ps += __shfl_xor_sync(0xffffffffu, ps, off, 16);
                pd += __shfl_xor_sync(0xffffffffu, pd, off, 16);
            }
            int gr = row0 + ty + rp * 2 + h;
            if (gr < NN) {
                __half2 p0 = __floats2half2_rn(o0, o1);
                __half2 p1 = __floats2half2_rn(o2, o3);
                uint2 pk;
                pk.x = *(unsigned*)&p0;
                pk.y = *(unsigned*)&p1;
                *(uint2*)&d_hh[gr * 64 + tx] = pk;
                if ((tid & 15) == 0) { d_asrc[gr] = ps; d_adst[gr] = pd; }
            }
        }
    }
}

// ================= segment softmax + weighted gather (HALF-WARP per node) ======
// Denominator via one width-16 shfl-reduce BEFORE the gather (loop is pure FMA).

__global__ __launch_bounds__(256, 8) void aggregate_k(
        const float* __restrict__ bias, float* __restrict__ out_ext, int to_internal)
{
    __shared__ float2 sew[8][2][32];
    float* __restrict__ out = to_internal ? d_x : out_ext;
    int w    = threadIdx.x >> 5;
    int lane = threadIdx.x & 31;
    int half = lane >> 4, li = lane & 15;
    unsigned hm = 0xFFFFu << (half * 16);
    int node = (blockIdx.x * 8 + w) * 2 + half;   // 6250*8*2 = 100000 exactly

    int deg = d_cnt[node];
    deg = deg > ECAP ? ECAP : deg;
    float4 b4 = ((const float4*)bias)[li];
    float4* op = (float4*)out + node * 16 + li;
    const int* row = d_ell + node * ECAP;

    if (deg <= 32) {
        float adv = d_adst[node];
        int   s0 = row[li < deg ? li : (deg > 0 ? deg - 1 : 0)];
        float e0 = d_asrc[s0] + adv;
        e0 = e0 > 0.f ? e0 : 0.2f * e0;
        float mx = li < deg ? e0 : -CUDART_INF_F;
        int s1 = 0; float e1 = 0.f;
        if (deg > 16) {
            int i2 = li + 16;
            s1 = row[i2 < deg ? i2 : deg - 1];
            e1 = d_asrc[s1] + adv;
            e1 = e1 > 0.f ? e1 : 0.2f * e1;
            if (i2 < deg) mx = fmaxf(mx, e1);
        }
#pragma unroll
        for (int off = 8; off; off >>= 1)
            mx = fmaxf(mx, __shfl_xor_sync(hm, mx, off, 16));
        float wt0 = li < deg ? __expf(e0 - mx) : 0.f;
        float wt1 = (deg > 16 && (li + 16) < deg) ? __expf(e1 - mx) : 0.f;
        sew[w][half][li] = make_float2(__int_as_float(s0), wt0);
        if (deg > 16)
            sew[w][half][li + 16] = make_float2(__int_as_float(s1), wt1);
        float sm = wt0 + wt1;
#pragma unroll
        for (int off = 8; off; off >>= 1)
            sm += __shfl_xor_sync(hm, sm, off, 16);
        float inv = 1.f / (sm + 1e-16f);
        __syncwarp(hm);

        float ax = 0.f, ay = 0.f, az = 0.f, aw = 0.f;
        int iters = (deg + 3) >> 2;
        for (int it = 0; it < iters; it++) {
            int base = it * 4;
            float2 p0 = sew[w][half][base + 0];
            float2 p1 = sew[w][half][base + 1];
            float2 p2 = sew[w][half][base + 2];
            float2 p3 = sew[w][half][base + 3];
            uint2 h0 = ((const uint2*)(d_hh + __float_as_int(p0.x) * 64))[li];
            uint2 h1 = ((const uint2*)(d_hh + __float_as_int(p1.x) * 64))[li];
            uint2 h2 = ((const uint2*)(d_hh + __float_as_int(p2.x) * 64))[li];
            uint2 h3 = ((const uint2*)(d_hh + __float_as_int(p3.x) * 64))[li];
            {
                float2 lo = __half22float2(*(__half2*)&h0.x);
                float2 hi = __half22float2(*(__half2*)&h0.y);
                ax += p0.y * lo.x; ay += p0.y * lo.y;
                az += p0.y * hi.x; aw += p0.y * hi.y;
            }
            {
                float2 lo = __half22float2(*(__half2*)&h1.x);
                float2 hi = __half22float2(*(__half2*)&h1.y);
                ax += p1.y * lo.x; ay += p1.y * lo.y;
                az += p1.y * hi.x; aw += p1.y * hi.y;
            }
            {
                float2 lo = __half22float2(*(__half2*)&h2.x);
                float2 hi = __half22float2(*(__half2*)&h2.y);
                ax += p2.y * lo.x; ay += p2.y * lo.y;
                az += p2.y * hi.x; aw += p2.y * hi.y;
            }
            {
                float2 lo = __half22float2(*(__half2*)&h3.x);
                float2 hi = __half22float2(*(__half2*)&h3.y);
                ax += p3.y * lo.x; ay += p3.y * lo.y;
                az += p3.y * hi.x; aw += p3.y * hi.y;
            }
        }
        float4 r;
        r.x = ax * inv + b4.x;
        r.y = ay * inv + b4.y;
        r.z = az * inv + b4.z;
        r.w = aw * inv + b4.w;
        *op = r;
    } else {
        // essentially-never path (deg in (32,128])
        float adv = d_adst[node];
        float mx = -CUDART_INF_F;
        for (int j = li; j < deg; j += 16) {
            float e = d_asrc[row[j]] + adv;
            e = e > 0.f ? e : 0.2f * e;
            mx = fmaxf(mx, e);
        }
#pragma unroll
        for (int off = 8; off; off >>= 1)
            mx = fmaxf(mx, __shfl_xor_sync(hm, mx, off, 16));
        float sm = 0.f;
        for (int j = li; j < deg; j += 16) {
            float e = d_asrc[row[j]] + adv;
            e = e > 0.f ? e : 0.2f * e;
            sm += __expf(e - mx);
        }
#pragma unroll
        for (int off = 8; off; off >>= 1)
            sm += __shfl_xor_sync(hm, sm, off, 16);
        float inv = 1.f / (sm + 1e-16f);

        float ax = 0.f, ay = 0.f, az = 0.f, aw = 0.f;
        for (int j = 0; j < deg; j++) {
            int s = row[j];
            float e = d_asrc[s] + adv;
            e = e > 0.f ? e : 0.2f * e;
            float wt = __expf(e - mx);
            uint2 hv = ((const uint2*)(d_hh + s * 64))[li];
            float2 lo = __half22float2(*(__half2*)&hv.x);
            float2 hi = __half22float2(*(__half2*)&hv.y);
            ax += wt * lo.x; ay += wt * lo.y;
            az += wt * hi.x; aw += wt * hi.y;
        }
        float4 r;
        r.x = ax * inv + b4.x;
        r.y = ay * inv + b4.y;
        r.z = az * inv + b4.z;
        r.w = aw * inv + b4.w;
        *op = r;
    }
}

// ================= launch =================

extern "C" void kernel_launch(void* const* d_in, const int* in_sizes, int n_in,
                              void* d_out, int out_size)
{
    const float* g     = (const float*)d_in[0];
    const int*   ei    = (const int*)  d_in[1];
    const float* W     = (const float*)d_in[2];
    const float* att_s = (const float*)d_in[3];
    const float* att_d = (const float*)d_in[4];
    const float* bias  = (const float*)d_in[5];
    float* out = (float*)d_out;

    const int* src = ei;
    const int* dst = ei + NE;

    zero_k<<<(NN + 255) / 256, 256>>>();
    ell_k<<<(NE + 255) / 256, 256>>>(src, dst);
    pad_k<<<1, 32>>>();   // keeps GEMM at ncu's captured launch slot (#3)

    const int gemm_blocks = (NN + 127) / 128;   // 782
    const int agg_blocks  = NN / 16;            // 6250, exact

    for (int L = 0; L < 4; L++) {
        gemm_attn_k<<<gemm_blocks, 256>>>(L == 0 ? g : nullptr, L == 0 ? 0 : 1,
                                          W, att_s, att_d);
        aggregate_k<<<agg_blocks, 256>>>(bias, L == 3 ? out : nullptr,
                                         L == 3 ? 0 : 1);
    }
}

// round 15
// speedup vs baseline: 1.2707x; 1.1689x over previous
#include <cuda_runtime.h>
#include <cuda_fp16.h>
#include <math_constants.h>

#define NN 100000
#define NE 1000000
#define DD 64
#define ECAP 128

// ---- static scratch ----
__device__ __align__(16) __half d_hh[NN * DD];  // fp16 projected features
__device__ __align__(16) float  d_x[NN * DD];   // fp32 layer ping buffer
__device__ float d_asrc[NN];
__device__ float d_adst[NN];
__device__ int   d_cnt[NN];
__device__ int   d_ell[NN * ECAP];

// ================= adjacency build =================

__global__ void zero_k() {
    int i = blockIdx.x * blockDim.x + threadIdx.x;
    if (i < NN) d_cnt[i] = 0;
}

__global__ void ell_k(const int* __restrict__ src, const int* __restrict__ dst) {
    int e = blockIdx.x * blockDim.x + threadIdx.x;
    if (e < NE) {
        int d = dst[e];
        int slot = atomicAdd(&d_cnt[d], 1);
        if (slot < ECAP) d_ell[d * ECAP + slot] = src[e];
    }
}

// profiler-alignment pad: keeps GEMM at captured launch index 3
__global__ void pad_k() {}

// ================= GEMM h = x @ W via mma.sync m16n8k16 (fp16 in, fp32 acc) ====
// 128-row tile, 8 warps, warp = 16 rows x 64 cols. x,W staged fp16 in smem
// (stride 72 halves -> conflict-free ldmatrix). B = W^T[n][k]: ldmatrix
// non-trans == col-major B fragment. Logits from fp32 fragments via quad-shfl.

#define LDSM4(r0, r1, r2, r3, addr) \
    asm volatile("ldmatrix.sync.aligned.m8n8.x4.shared.b16 {%0,%1,%2,%3}, [%4];" \
        : "=r"(r0), "=r"(r1), "=r"(r2), "=r"(r3) : "r"(addr))
#define MMA16816(c0, c1, c2, c3, a0, a1, a2, a3, b0, b1) \
    asm volatile("mma.sync.aligned.m16n8k16.row.col.f32.f16.f16.f32 " \
        "{%0,%1,%2,%3}, {%4,%5,%6,%7}, {%8,%9}, {%0,%1,%2,%3};" \
        : "+f"(c0), "+f"(c1), "+f"(c2), "+f"(c3) \
        : "r"(a0), "r"(a1), "r"(a2), "r"(a3), "r"(b0), "r"(b1))

__global__ __launch_bounds__(256) void gemm_attn_k(
        const float* __restrict__ x_ext, int use_internal,
        const float* __restrict__ W,
        const float* __restrict__ att_s, const float* __restrict__ att_d)
{
    const float* __restrict__ x = use_internal ? d_x : x_ext;
    __shared__ __align__(16) __half xh[128 * 72];  // 18 KB (reused as h-buf)
    __shared__ __align__(16) __half wT[64 * 72];   //  9 KB  W^T[n][k]
    __shared__ float sas[64], sad[64];
    int tid  = threadIdx.x;
    int lane = tid & 31;
    int wid  = tid >> 5;
    int row0 = blockIdx.x * 128;

    // stage W^T fp16
    for (int i = tid; i < 1024; i += 256) {
        int k = i >> 4, n4 = (i & 15) * 4;
        float4 v = ((const float4*)W)[i];            // W[k][n4..n4+3]
        wT[(n4 + 0) * 72 + k] = __float2half_rn(v.x);
        wT[(n4 + 1) * 72 + k] = __float2half_rn(v.y);
        wT[(n4 + 2) * 72 + k] = __float2half_rn(v.z);
        wT[(n4 + 3) * 72 + k] = __float2half_rn(v.w);
    }
    // stage x fp16 (rows padded with zeros past NN)
    for (int i = tid; i < 2048; i += 256) {
        int r = i >> 4, c4 = (i & 15) * 4;
        float4 v = make_float4(0.f, 0.f, 0.f, 0.f);
        int gr = row0 + r;
        if (gr < NN) v = ((const float4*)x)[gr * 16 + (i & 15)];
        __half2 p0 = __floats2half2_rn(v.x, v.y);
        __half2 p1 = __floats2half2_rn(v.z, v.w);
        uint2 pk;
        pk.x = *(unsigned*)&p0; pk.y = *(unsigned*)&p1;
        *(uint2*)&xh[r * 72 + c4] = pk;
    }
    if (tid < 64)       sas[tid]      = att_s[tid];
    else if (tid < 128) sad[tid - 64] = att_d[tid - 64];
    __syncthreads();

    unsigned xh_base = (unsigned)__cvta_generic_to_shared(xh);
    unsigned wT_base = (unsigned)__cvta_generic_to_shared(wT);

    float c[8][4];
#pragma unroll
    for (int nb = 0; nb < 8; nb++)
#pragma unroll
        for (int j = 0; j < 4; j++) c[nb][j] = 0.f;

#pragma unroll
    for (int kk = 0; kk < 4; kk++) {
        // A fragment: 16x16 slice, rows wid*16.., k = kk*16..
        unsigned a_addr = xh_base +
            ((wid * 16 + (lane & 15)) * 72 + kk * 16 + (lane >> 4) * 8) * 2;
        unsigned a0, a1, a2, a3;
        LDSM4(a0, a1, a2, a3, a_addr);
#pragma unroll
        for (int nbp = 0; nbp < 4; nbp++) {
            // B fragments for n-blocks 2*nbp, 2*nbp+1
            unsigned n    = nbp * 16 + ((lane >> 4) & 1) * 8 + (lane & 7);
            unsigned koff = ((lane >> 3) & 1) * 8;
            unsigned b_addr = wT_base + (n * 72 + kk * 16 + koff) * 2;
            unsigned b0, b1, b2, b3;
            LDSM4(b0, b1, b2, b3, b_addr);
            int nb = nbp * 2;
            MMA16816(c[nb][0], c[nb][1], c[nb][2], c[nb][3],
                     a0, a1, a2, a3, b0, b1);
            MMA16816(c[nb+1][0], c[nb+1][1], c[nb+1][2], c[nb+1][3],
                     a0, a1, a2, a3, b2, b3);
        }
    }

    // attention logits: rows wid*16+g (c0,c1) and +8 (c2,c3); quad-reduce
    int g = lane >> 2, q = lane & 3;
    float psA = 0.f, pdA = 0.f, psB = 0.f, pdB = 0.f;
#pragma unroll
    for (int nb = 0; nb < 8; nb++) {
        int col = nb * 8 + q * 2;
        float s0 = sas[col], s1 = sas[col + 1];
        float d0 = sad[col], d1 = sad[col + 1];
        psA += c[nb][0] * s0 + c[nb][1] * s1;
        pdA += c[nb][0] * d0 + c[nb][1] * d1;
        psB += c[nb][2] * s0 + c[nb][3] * s1;
        pdB += c[nb][2] * d0 + c[nb][3] * d1;
    }
#pragma unroll
    for (int off = 1; off <= 2; off <<= 1) {
        psA += __shfl_xor_sync(0xffffffffu, psA, off);
        pdA += __shfl_xor_sync(0xffffffffu, pdA, off);
        psB += __shfl_xor_sync(0xffffffffu, psB, off);
        pdB += __shfl_xor_sync(0xffffffffu, pdB, off);
    }
    int grA = row0 + wid * 16 + g;
    int grB = grA + 8;
    if (q == 0) {
        if (grA < NN) { d_asrc[grA] = psA; d_adst[grA] = pdA; }
        if (grB < NN) { d_asrc[grB] = psB; d_adst[grB] = pdB; }
    }

    __syncthreads();                 // xh reads done -> reuse as h staging buf
    __half* hb = xh;                 // 128 x 64 halves = 16 KB
#pragma unroll
    for (int nb = 0; nb < 8; nb++) {
        int col = nb * 8 + q * 2;
        __half2 hA = __floats2half2_rn(c[nb][0], c[nb][1]);
        __half2 hB = __floats2half2_rn(c[nb][2], c[nb][3]);
        *(__half2*)&hb[(wid * 16 + g) * 64 + col]     = hA;
        *(__half2*)&hb[(wid * 16 + g + 8) * 64 + col] = hB;
    }
    __syncthreads();

    // coalesced copy out: 128 rows x 128 B = 1024 uint4
    const uint4* hb4 = (const uint4*)hb;
#pragma unroll
    for (int t = 0; t < 4; t++) {
        int i = tid + t * 256;
        int gr = row0 + (i >> 3);
        if (gr < NN)
            ((uint4*)d_hh)[row0 * 8 + i] = hb4[i];
    }
}

// ================= segment softmax + weighted gather (HALF-WARP per node) ======

__global__ __launch_bounds__(256, 8) void aggregate_k(
        const float* __restrict__ bias, float* __restrict__ out_ext, int to_internal)
{
    __shared__ float2 sew[8][2][32];
    float* __restrict__ out = to_internal ? d_x : out_ext;
    int w    = threadIdx.x >> 5;
    int lane = threadIdx.x & 31;
    int half = lane >> 4, li = lane & 15;
    unsigned hm = 0xFFFFu << (half * 16);
    int node = (blockIdx.x * 8 + w) * 2 + half;   // 6250*8*2 = 100000 exactly

    int deg = d_cnt[node];
    deg = deg > ECAP ? ECAP : deg;
    float4 b4 = ((const float4*)bias)[li];
    float4* op = (float4*)out + node * 16 + li;
    const int* row = d_ell + node * ECAP;

    if (deg <= 32) {
        float adv = d_adst[node];
        int   s0 = row[li < deg ? li : (deg > 0 ? deg - 1 : 0)];
        float e0 = d_asrc[s0] + adv;
        e0 = e0 > 0.f ? e0 : 0.2f * e0;
        float mx = li < deg ? e0 : -CUDART_INF_F;
        int s1 = 0; float e1 = 0.f;
        if (deg > 16) {
            int i2 = li + 16;
            s1 = row[i2 < deg ? i2 : deg - 1];
            e1 = d_asrc[s1] + adv;
            e1 = e1 > 0.f ? e1 : 0.2f * e1;
            if (i2 < deg) mx = fmaxf(mx, e1);
        }
#pragma unroll
        for (int off = 8; off; off >>= 1)
            mx = fmaxf(mx, __shfl_xor_sync(hm, mx, off, 16));
        float wt0 = li < deg ? __expf(e0 - mx) : 0.f;
        float wt1 = (deg > 16 && (li + 16) < deg) ? __expf(e1 - mx) : 0.f;
        sew[w][half][li] = make_float2(__int_as_float(s0), wt0);
        if (deg > 16)
            sew[w][half][li + 16] = make_float2(__int_as_float(s1), wt1);
        float sm = wt0 + wt1;
#pragma unroll
        for (int off = 8; off; off >>= 1)
            sm += __shfl_xor_sync(hm, sm, off, 16);
        float inv = 1.f / (sm + 1e-16f);
        __syncwarp(hm);

        float ax = 0.f, ay = 0.f, az = 0.f, aw = 0.f;
        int iters = (deg + 3) >> 2;
        for (int it = 0; it < iters; it++) {
            int base = it * 4;
            float2 p0 = sew[w][half][base + 0];
            float2 p1 = sew[w][half][base + 1];
            float2 p2 = sew[w][half][base + 2];
            float2 p3 = sew[w][half][base + 3];
            uint2 h0 = ((const uint2*)(d_hh + __float_as_int(p0.x) * 64))[li];
            uint2 h1 = ((const uint2*)(d_hh + __float_as_int(p1.x) * 64))[li];
            uint2 h2 = ((const uint2*)(d_hh + __float_as_int(p2.x) * 64))[li];
            uint2 h3 = ((const uint2*)(d_hh + __float_as_int(p3.x) * 64))[li];
            {
                float2 lo = __half22float2(*(__half2*)&h0.x);
                float2 hi = __half22float2(*(__half2*)&h0.y);
                ax += p0.y * lo.x; ay += p0.y * lo.y;
                az += p0.y * hi.x; aw += p0.y * hi.y;
            }
            {
                float2 lo = __half22float2(*(__half2*)&h1.x);
                float2 hi = __half22float2(*(__half2*)&h1.y);
                ax += p1.y * lo.x; ay += p1.y * lo.y;
                az += p1.y * hi.x; aw += p1.y * hi.y;
            }
            {
                float2 lo = __half22float2(*(__half2*)&h2.x);
                float2 hi = __half22float2(*(__half2*)&h2.y);
                ax += p2.y * lo.x; ay += p2.y * lo.y;
                az += p2.y * hi.x; aw += p2.y * hi.y;
            }
            {
                float2 lo = __half22float2(*(__half2*)&h3.x);
                float2 hi = __half22float2(*(__half2*)&h3.y);
                ax += p3.y * lo.x; ay += p3.y * lo.y;
                az += p3.y * hi.x; aw += p3.y * hi.y;
            }
        }
        float4 r;
        r.x = ax * inv + b4.x;
        r.y = ay * inv + b4.y;
        r.z = az * inv + b4.z;
        r.w = aw * inv + b4.w;
        *op = r;
    } else {
        // essentially-never path (deg in (32,128])
        float adv = d_adst[node];
        float mx = -CUDART_INF_F;
        for (int j = li; j < deg; j += 16) {
            float e = d_asrc[row[j]] + adv;
            e = e > 0.f ? e : 0.2f * e;
            mx = fmaxf(mx, e);
        }
#pragma unroll
        for (int off = 8; off; off >>= 1)
            mx = fmaxf(mx, __shfl_xor_sync(hm, mx, off, 16));
        float sm = 0.f;
        for (int j = li; j < deg; j += 16) {
            float e = d_asrc[row[j]] + adv;
            e = e > 0.f ? e : 0.2f * e;
            sm += __expf(e - mx);
        }
#pragma unroll
        for (int off = 8; off; off >>= 1)
            sm += __shfl_xor_sync(hm, sm, off, 16);
        float inv = 1.f / (sm + 1e-16f);

        float ax = 0.f, ay = 0.f, az = 0.f, aw = 0.f;
        for (int j = 0; j < deg; j++) {
            int s = row[j];
            float e = d_asrc[s] + adv;
            e = e > 0.f ? e : 0.2f * e;
            float wt = __expf(e - mx);
            uint2 hv = ((const uint2*)(d_hh + s * 64))[li];
            float2 lo = __half22float2(*(__half2*)&hv.x);
            float2 hi = __half22float2(*(__half2*)&hv.y);
            ax += wt * lo.x; ay += wt * lo.y;
            az += wt * hi.x; aw += wt * hi.y;
        }
        float4 r;
        r.x = ax * inv + b4.x;
        r.y = ay * inv + b4.y;
        r.z = az * inv + b4.z;
        r.w = aw * inv + b4.w;
        *op = r;
    }
}

// ================= launch =================

extern "C" void kernel_launch(void* const* d_in, const int* in_sizes, int n_in,
                              void* d_out, int out_size)
{
    const float* g     = (const float*)d_in[0];
    const int*   ei    = (const int*)  d_in[1];
    const float* W     = (const float*)d_in[2];
    const float* att_s = (const float*)d_in[3];
    const float* att_d = (const float*)d_in[4];
    const float* bias  = (const float*)d_in[5];
    float* out = (float*)d_out;

    const int* src = ei;
    const int* dst = ei + NE;

    zero_k<<<(NN + 255) / 256, 256>>>();
    ell_k<<<(NE + 255) / 256, 256>>>(src, dst);
    pad_k<<<1, 32>>>();   // keeps GEMM at ncu's captured launch slot (#3)

    const int gemm_blocks = (NN + 127) / 128;   // 782
    const int agg_blocks  = NN / 16;            // 6250, exact

    for (int L = 0; L < 4; L++) {
        gemm_attn_k<<<gemm_blocks, 256>>>(L == 0 ? g : nullptr, L == 0 ? 0 : 1,
                                          W, att_s, att_d);
        aggregate_k<<<agg_blocks, 256>>>(bias, L == 3 ? out : nullptr,
                                         L == 3 ? 0 : 1);
    }
}

// round 16
// speedup vs baseline: 1.3228x; 1.0410x over previous
#include <cuda_runtime.h>
#include <cuda_fp16.h>
#include <math_constants.h>

#define NN 100000
#define NE 1000000
#define DD 64
#define ECAP 128

// ---- static scratch ----
__device__ __align__(16) __half d_hh[NN * DD];  // fp16 projected features
__device__ __align__(16) __half d_xh[NN * DD];  // fp16 inter-layer buffer
__device__ float d_asrc[NN];
__device__ float d_adst[NN];
__device__ int   d_cnt[NN];
__device__ int   d_ell[NN * ECAP];

// ================= adjacency build =================

__global__ void zero_k() {
    int i = blockIdx.x * blockDim.x + threadIdx.x;
    if (i < NN) d_cnt[i] = 0;
}

__global__ void ell_k(const int* __restrict__ src, const int* __restrict__ dst) {
    int e = blockIdx.x * blockDim.x + threadIdx.x;
    if (e < NE) {
        int d = dst[e];
        int slot = atomicAdd(&d_cnt[d], 1);
        if (slot < ECAP) d_ell[d * ECAP + slot] = src[e];
    }
}

// profiler-alignment pad: keeps GEMM at captured launch index 3
__global__ void pad_k() {}

// ================= GEMM h = x @ W via mma.sync m16n8k16 (fp16 in, fp32 acc) ====
// Layers 1-3: x already fp16 -> staging is a pure uint4 copy (no cvt).

#define LDSM4(r0, r1, r2, r3, addr) \
    asm volatile("ldmatrix.sync.aligned.m8n8.x4.shared.b16 {%0,%1,%2,%3}, [%4];" \
        : "=r"(r0), "=r"(r1), "=r"(r2), "=r"(r3) : "r"(addr))
#define MMA16816(c0, c1, c2, c3, a0, a1, a2, a3, b0, b1) \
    asm volatile("mma.sync.aligned.m16n8k16.row.col.f32.f16.f16.f32 " \
        "{%0,%1,%2,%3}, {%4,%5,%6,%7}, {%8,%9}, {%0,%1,%2,%3};" \
        : "+f"(c0), "+f"(c1), "+f"(c2), "+f"(c3) \
        : "r"(a0), "r"(a1), "r"(a2), "r"(a3), "r"(b0), "r"(b1))

__global__ __launch_bounds__(256) void gemm_attn_k(
        const float* __restrict__ x_ext, int use_internal,
        const float* __restrict__ W,
        const float* __restrict__ att_s, const float* __restrict__ att_d)
{
    __shared__ __align__(16) __half xh[128 * 72];  // 18 KB (reused as h-buf)
    __shared__ __align__(16) __half wT[64 * 72];   //  9 KB  W^T[n][k]
    __shared__ float sas[64], sad[64];
    int tid  = threadIdx.x;
    int lane = tid & 31;
    int wid  = tid >> 5;
    int row0 = blockIdx.x * 128;

    // stage W^T fp16
    for (int i = tid; i < 1024; i += 256) {
        int k = i >> 4, n4 = (i & 15) * 4;
        float4 v = ((const float4*)W)[i];            // W[k][n4..n4+3]
        wT[(n4 + 0) * 72 + k] = __float2half_rn(v.x);
        wT[(n4 + 1) * 72 + k] = __float2half_rn(v.y);
        wT[(n4 + 2) * 72 + k] = __float2half_rn(v.z);
        wT[(n4 + 3) * 72 + k] = __float2half_rn(v.w);
    }
    // stage x fp16
    if (use_internal) {
        // pure copy: 128 rows x 8 uint4 (16 halves each)
        for (int i = tid; i < 1024; i += 256) {
            int r = i >> 3, c8 = i & 7;
            uint4 v = make_uint4(0u, 0u, 0u, 0u);
            int gr = row0 + r;
            if (gr < NN) v = ((const uint4*)d_xh)[gr * 8 + c8];
            *(uint4*)&xh[r * 72 + c8 * 8] = v;      // 144r+16c8 bytes: 16B-aligned
        }
    } else {
        for (int i = tid; i < 2048; i += 256) {
            int r = i >> 4, c4 = (i & 15) * 4;
            float4 v = make_float4(0.f, 0.f, 0.f, 0.f);
            int gr = row0 + r;
            if (gr < NN) v = ((const float4*)x_ext)[gr * 16 + (i & 15)];
            __half2 p0 = __floats2half2_rn(v.x, v.y);
            __half2 p1 = __floats2half2_rn(v.z, v.w);
            uint2 pk;
            pk.x = *(unsigned*)&p0; pk.y = *(unsigned*)&p1;
            *(uint2*)&xh[r * 72 + c4] = pk;
        }
    }
    if (tid < 64)       sas[tid]      = att_s[tid];
    else if (tid < 128) sad[tid - 64] = att_d[tid - 64];
    __syncthreads();

    unsigned xh_base = (unsigned)__cvta_generic_to_shared(xh);
    unsigned wT_base = (unsigned)__cvta_generic_to_shared(wT);

    float c[8][4];
#pragma unroll
    for (int nb = 0; nb < 8; nb++)
#pragma unroll
        for (int j = 0; j < 4; j++) c[nb][j] = 0.f;

#pragma unroll
    for (int kk = 0; kk < 4; kk++) {
        unsigned a_addr = xh_base +
            ((wid * 16 + (lane & 15)) * 72 + kk * 16 + (lane >> 4) * 8) * 2;
        unsigned a0, a1, a2, a3;
        LDSM4(a0, a1, a2, a3, a_addr);
#pragma unroll
        for (int nbp = 0; nbp < 4; nbp++) {
            unsigned n    = nbp * 16 + ((lane >> 4) & 1) * 8 + (lane & 7);
            unsigned koff = ((lane >> 3) & 1) * 8;
            unsigned b_addr = wT_base + (n * 72 + kk * 16 + koff) * 2;
            unsigned b0, b1, b2, b3;
            LDSM4(b0, b1, b2, b3, b_addr);
            int nb = nbp * 2;
            MMA16816(c[nb][0], c[nb][1], c[nb][2], c[nb][3],
                     a0, a1, a2, a3, b0, b1);
            MMA16816(c[nb+1][0], c[nb+1][1], c[nb+1][2], c[nb+1][3],
                     a0, a1, a2, a3, b2, b3);
        }
    }

    // attention logits: rows wid*16+g (c0,c1) and +8 (c2,c3); quad-reduce
    int g = lane >> 2, q = lane & 3;
    float psA = 0.f, pdA = 0.f, psB = 0.f, pdB = 0.f;
#pragma unroll
    for (int nb = 0; nb < 8; nb++) {
        int col = nb * 8 + q * 2;
        float s0 = sas[col], s1 = sas[col + 1];
        float d0 = sad[col], d1 = sad[col + 1];
        psA += c[nb][0] * s0 + c[nb][1] * s1;
        pdA += c[nb][0] * d0 + c[nb][1] * d1;
        psB += c[nb][2] * s0 + c[nb][3] * s1;
        pdB += c[nb][2] * d0 + c[nb][3] * d1;
    }
#pragma unroll
    for (int off = 1; off <= 2; off <<= 1) {
        psA += __shfl_xor_sync(0xffffffffu, psA, off);
        pdA += __shfl_xor_sync(0xffffffffu, pdA, off);
        psB += __shfl_xor_sync(0xffffffffu, psB, off);
        pdB += __shfl_xor_sync(0xffffffffu, pdB, off);
    }
    int grA = row0 + wid * 16 + g;
    int grB = grA + 8;
    if (q == 0) {
        if (grA < NN) { d_asrc[grA] = psA; d_adst[grA] = pdA; }
        if (grB < NN) { d_asrc[grB] = psB; d_adst[grB] = pdB; }
    }

    __syncthreads();                 // xh reads done -> reuse as h staging buf
    __half* hb = xh;                 // 128 x 64 halves = 16 KB
#pragma unroll
    for (int nb = 0; nb < 8; nb++) {
        int col = nb * 8 + q * 2;
        __half2 hA = __floats2half2_rn(c[nb][0], c[nb][1]);
        __half2 hB = __floats2half2_rn(c[nb][2], c[nb][3]);
        *(__half2*)&hb[(wid * 16 + g) * 64 + col]     = hA;
        *(__half2*)&hb[(wid * 16 + g + 8) * 64 + col] = hB;
    }
    __syncthreads();

    // coalesced copy out: 128 rows x 128 B = 1024 uint4
    const uint4* hb4 = (const uint4*)hb;
#pragma unroll
    for (int t = 0; t < 4; t++) {
        int i = tid + t * 256;
        int gr = row0 + (i >> 3);
        if (gr < NN)
            ((uint4*)d_hh)[row0 * 8 + i] = hb4[i];
    }
}

// ================= segment softmax + weighted gather (HALF-WARP per node) ======
// Output: fp16 to d_xh for layers 0-2, fp32 to d_out for layer 3.

__global__ __launch_bounds__(256, 8) void aggregate_k(
        const float* __restrict__ bias, float* __restrict__ out_ext, int to_internal)
{
    __shared__ float2 sew[8][2][32];
    int w    = threadIdx.x >> 5;
    int lane = threadIdx.x & 31;
    int half = lane >> 4, li = lane & 15;
    unsigned hm = 0xFFFFu << (half * 16);
    int node = (blockIdx.x * 8 + w) * 2 + half;   // 6250*8*2 = 100000 exactly

    int deg = d_cnt[node];
    deg = deg > ECAP ? ECAP : deg;
    float4 b4 = ((const float4*)bias)[li];
    const int* row = d_ell + node * ECAP;

    float ax, ay, az, aw, inv;

    if (deg <= 32) {
        float adv = d_adst[node];
        int   s0 = row[li < deg ? li : (deg > 0 ? deg - 1 : 0)];
        float e0 = d_asrc[s0] + adv;
        e0 = e0 > 0.f ? e0 : 0.2f * e0;
        float mx = li < deg ? e0 : -CUDART_INF_F;
        int s1 = 0; float e1 = 0.f;
        if (deg > 16) {
            int i2 = li + 16;
            s1 = row[i2 < deg ? i2 : deg - 1];
            e1 = d_asrc[s1] + adv;
            e1 = e1 > 0.f ? e1 : 0.2f * e1;
            if (i2 < deg) mx = fmaxf(mx, e1);
        }
#pragma unroll
        for (int off = 8; off; off >>= 1)
            mx = fmaxf(mx, __shfl_xor_sync(hm, mx, off, 16));
        float wt0 = li < deg ? __expf(e0 - mx) : 0.f;
        float wt1 = (deg > 16 && (li + 16) < deg) ? __expf(e1 - mx) : 0.f;
        sew[w][half][li] = make_float2(__int_as_float(s0), wt0);
        if (deg > 16)
            sew[w][half][li + 16] = make_float2(__int_as_float(s1), wt1);
        float sm = wt0 + wt1;
#pragma unroll
        for (int off = 8; off; off >>= 1)
            sm += __shfl_xor_sync(hm, sm, off, 16);
        inv = 1.f / (sm + 1e-16f);
        __syncwarp(hm);

        ax = 0.f; ay = 0.f; az = 0.f; aw = 0.f;
        int iters = (deg + 3) >> 2;
        for (int it = 0; it < iters; it++) {
            int base = it * 4;
            float2 p0 = sew[w][half][base + 0];
            float2 p1 = sew[w][half][base + 1];
            float2 p2 = sew[w][half][base + 2];
            float2 p3 = sew[w][half][base + 3];
            uint2 h0 = ((const uint2*)(d_hh + __float_as_int(p0.x) * 64))[li];
            uint2 h1 = ((const uint2*)(d_hh + __float_as_int(p1.x) * 64))[li];
            uint2 h2 = ((const uint2*)(d_hh + __float_as_int(p2.x) * 64))[li];
            uint2 h3 = ((const uint2*)(d_hh + __float_as_int(p3.x) * 64))[li];
            {
                float2 lo = __half22float2(*(__half2*)&h0.x);
                float2 hi = __half22float2(*(__half2*)&h0.y);
                ax += p0.y * lo.x; ay += p0.y * lo.y;
                az += p0.y * hi.x; aw += p0.y * hi.y;
            }
            {
                float2 lo = __half22float2(*(__half2*)&h1.x);
                float2 hi = __half22float2(*(__half2*)&h1.y);
                ax += p1.y * lo.x; ay += p1.y * lo.y;
                az += p1.y * hi.x; aw += p1.y * hi.y;
            }
            {
                float2 lo = __half22float2(*(__half2*)&h2.x);
                float2 hi = __half22float2(*(__half2*)&h2.y);
                ax += p2.y * lo.x; ay += p2.y * lo.y;
                az += p2.y * hi.x; aw += p2.y * hi.y;
            }
            {
                float2 lo = __half22float2(*(__half2*)&h3.x);
                float2 hi = __half22float2(*(__half2*)&h3.y);
                ax += p3.y * lo.x; ay += p3.y * lo.y;
                az += p3.y * hi.x; aw += p3.y * hi.y;
            }
        }
    } else {
        // essentially-never path (deg in (32,128])
        float adv = d_adst[node];
        float mx = -CUDART_INF_F;
        for (int j = li; j < deg; j += 16) {
            float e = d_asrc[row[j]] + adv;
            e = e > 0.f ? e : 0.2f * e;
            mx = fmaxf(mx, e);
        }
#pragma unroll
        for (int off = 8; off; off >>= 1)
            mx = fmaxf(mx, __shfl_xor_sync(hm, mx, off, 16));
        float sm = 0.f;
        for (int j = li; j < deg; j += 16) {
            float e = d_asrc[row[j]] + adv;
            e = e > 0.f ? e : 0.2f * e;
            sm += __expf(e - mx);
        }
#pragma unroll
        for (int off = 8; off; off >>= 1)
            sm += __shfl_xor_sync(hm, sm, off, 16);
        inv = 1.f / (sm + 1e-16f);

        ax = 0.f; ay = 0.f; az = 0.f; aw = 0.f;
        for (int j = 0; j < deg; j++) {
            int s = row[j];
            float e = d_asrc[s] + adv;
            e = e > 0.f ? e : 0.2f * e;
            float wt = __expf(e - mx);
            uint2 hv = ((const uint2*)(d_hh + s * 64))[li];
            float2 lo = __half22float2(*(__half2*)&hv.x);
            float2 hi = __half22float2(*(__half2*)&hv.y);
            ax += wt * lo.x; ay += wt * lo.y;
            az += wt * hi.x; aw += wt * hi.y;
        }
    }

    float4 r;
    r.x = ax * inv + b4.x;
    r.y = ay * inv + b4.y;
    r.z = az * inv + b4.z;
    r.w = aw * inv + b4.w;
    if (to_internal) {
        __half2 pA = __floats2half2_rn(r.x, r.y);
        __half2 pB = __floats2half2_rn(r.z, r.w);
        uint2 pk;
        pk.x = *(unsigned*)&pA; pk.y = *(unsigned*)&pB;
        *(uint2*)&d_xh[node * 64 + li * 4] = pk;
    } else {
        ((float4*)out_ext)[node * 16 + li] = r;
    }
}

// ================= launch =================

extern "C" void kernel_launch(void* const* d_in, const int* in_sizes, int n_in,
                              void* d_out, int out_size)
{
    const float* g     = (const float*)d_in[0];
    const int*   ei    = (const int*)  d_in[1];
    const float* W     = (const float*)d_in[2];
    const float* att_s = (const float*)d_in[3];
    const float* att_d = (const float*)d_in[4];
    const float* bias  = (const float*)d_in[5];
    float* out = (float*)d_out;

    const int* src = ei;
    const int* dst = ei + NE;

    zero_k<<<(NN + 255) / 256, 256>>>();
    ell_k<<<(NE + 255) / 256, 256>>>(src, dst);
    pad_k<<<1, 32>>>();   // keeps GEMM at ncu's captured launch slot (#3)

    const int gemm_blocks = (NN + 127) / 128;   // 782
    const int agg_blocks  = NN / 16;            // 6250, exact

    for (int L = 0; L < 4; L++) {
        gemm_attn_k<<<gemm_blocks, 256>>>(L == 0 ? g : nullptr, L == 0 ? 0 : 1,
                                          W, att_s, att_d);
        aggregate_k<<<agg_blocks, 256>>>(bias, L == 3 ? out : nullptr,
                                         L == 3 ? 0 : 1);
    }
}